// round 16
// baseline (speedup 1.0000x reference)
#include <cuda_runtime.h>
#include <cuda_bf16.h>
#include <cuda_fp16.h>
#include <math.h>
#include <stdint.h>

// Problem constants
#define BATCH   2
#define SEQ     2048
#define DMODEL  1024
#define HEADS   16
#define DHEAD   64
#define INNER   (HEADS*DHEAD)      // 1024
#define ROWS    (BATCH*SEQ)        // 4096
#define ATT_SCALE 0.125f
#define MASK_NEG 1000000.0f
#define INV2048 4.8828125e-4f

// ---------------------------------------------------------------------------
// Scratch (allocation-free rule: static __device__ globals)
// ---------------------------------------------------------------------------
__device__ float g_q[ROWS*INNER];
// flash K/V operands, per-head layout [b][h][key][64]
__device__ __half        g_kh[ROWS*INNER];
__device__ __half        g_kl[ROWS*INNER];   // (k - hi) * 2048
__device__ __nv_bfloat16 g_vh[ROWS*INNER];
__device__ __nv_bfloat16 g_vl[ROWS*INNER];
// pre-split GEMM operands (fp16: lo scaled by 2048)
__device__ __half g_xfh[ROWS*DMODEL],  g_xfl[ROWS*DMODEL];
__device__ __half g_ctfh[ROWS*DMODEL], g_ctfl[ROWS*DMODEL];
__device__ __half g_wqfh[DMODEL*INNER], g_wqfl[DMODEL*INNER];
__device__ __half g_wkfh[DMODEL*INNER], g_wkfl[DMODEL*INNER];
__device__ __nv_bfloat16 g_ctbh[ROWS*DMODEL], g_ctbl[ROWS*DMODEL];
__device__ __nv_bfloat16 g_wvbh[DMODEL*INNER], g_wvbl[DMODEL*INNER];
__device__ __nv_bfloat16 g_wobh[INNER*DMODEL], g_wobl[INNER*DMODEL];
__device__ __nv_bfloat16 g_obh[ROWS*INNER], g_obl[ROWS*INNER];

// ---------------------------------------------------------------------------
// mma.sync / ldmatrix / cp.async helpers (compute_103-compatible; NO tcgen05)
// ---------------------------------------------------------------------------
__device__ __forceinline__ void mma_bf16(float* d, const uint32_t* a,
                                         uint32_t b0, uint32_t b1)
{
    asm volatile(
        "mma.sync.aligned.m16n8k16.row.col.f32.bf16.bf16.f32 "
        "{%0,%1,%2,%3}, {%4,%5,%6,%7}, {%8,%9}, {%0,%1,%2,%3};"
        : "+f"(d[0]), "+f"(d[1]), "+f"(d[2]), "+f"(d[3])
        : "r"(a[0]), "r"(a[1]), "r"(a[2]), "r"(a[3]), "r"(b0), "r"(b1));
}

__device__ __forceinline__ void mma_fp16(float* d, const uint32_t* a,
                                         uint32_t b0, uint32_t b1)
{
    asm volatile(
        "mma.sync.aligned.m16n8k16.row.col.f32.f16.f16.f32 "
        "{%0,%1,%2,%3}, {%4,%5,%6,%7}, {%8,%9}, {%0,%1,%2,%3};"
        : "+f"(d[0]), "+f"(d[1]), "+f"(d[2]), "+f"(d[3])
        : "r"(a[0]), "r"(a[1]), "r"(a[2]), "r"(a[3]), "r"(b0), "r"(b1));
}

__device__ __forceinline__ uint32_t pack_bf16x2(float lo_val, float hi_val) {
    uint32_t r;
    asm("cvt.rn.bf16x2.f32 %0, %1, %2;" : "=r"(r) : "f"(hi_val), "f"(lo_val));
    return r;
}

__device__ __forceinline__ uint32_t pack_f16x2(float lo_val, float hi_val) {
    __half h0 = __float2half_rn(lo_val);
    __half h1 = __float2half_rn(hi_val);
    return ((uint32_t)__half_as_ushort(h1) << 16) | __half_as_ushort(h0);
}

__device__ __forceinline__ void ldmx4t(uint32_t& r0, uint32_t& r1,
                                       uint32_t& r2, uint32_t& r3, uint32_t addr)
{
    asm volatile(
        "ldmatrix.sync.aligned.m8n8.x4.trans.shared.b16 {%0,%1,%2,%3}, [%4];"
        : "=r"(r0), "=r"(r1), "=r"(r2), "=r"(r3) : "r"(addr));
}
__device__ __forceinline__ void ldmx4(uint32_t& r0, uint32_t& r1,
                                      uint32_t& r2, uint32_t& r3, uint32_t addr)
{
    asm volatile(
        "ldmatrix.sync.aligned.m8n8.x4.shared.b16 {%0,%1,%2,%3}, [%4];"
        : "=r"(r0), "=r"(r1), "=r"(r2), "=r"(r3) : "r"(addr));
}

__device__ __forceinline__ void cp_async16(uint32_t saddr, const void* gptr) {
    asm volatile("cp.async.cg.shared.global [%0], [%1], 16;"
                 :: "r"(saddr), "l"(gptr));
}
__device__ __forceinline__ void cp_async_commit() {
    asm volatile("cp.async.commit_group;");
}
__device__ __forceinline__ void cp_async_wait0() {
    asm volatile("cp.async.wait_group 0;");
}
__device__ __forceinline__ void cp_async_wait1() {
    asm volatile("cp.async.wait_group 1;");
}

// ===========================================================================
// One-time operand split kernels
// ===========================================================================
__global__ void split_f16(const float* __restrict__ src,
                          __half* __restrict__ hi, __half* __restrict__ lo,
                          int n4)
{
    int i = blockIdx.x * blockDim.x + threadIdx.x;
    if (i >= n4) return;
    float4 x = ((const float4*)src)[i];
    float a[4] = {x.x, x.y, x.z, x.w};
    uint32_t hp[2], lp[2];
    #pragma unroll
    for (int p = 0; p < 2; p++) {
        __half h0 = __float2half_rn(a[2*p]);
        __half h1 = __float2half_rn(a[2*p+1]);
        hp[p] = ((uint32_t)__half_as_ushort(h1) << 16) | __half_as_ushort(h0);
        lp[p] = pack_f16x2((a[2*p]   - __half2float(h0)) * 2048.f,
                           (a[2*p+1] - __half2float(h1)) * 2048.f);
    }
    ((uint2*)hi)[i] = make_uint2(hp[0], hp[1]);
    ((uint2*)lo)[i] = make_uint2(lp[0], lp[1]);
}

__global__ void split_f16_slice(const float* __restrict__ src,
                                __half* __restrict__ hi, __half* __restrict__ lo,
                                int cols_src, int col0)
{
    int i = blockIdx.x * blockDim.x + threadIdx.x;
    if (i >= DMODEL * INNER / 4) return;
    int e = i * 4;
    int r = e >> 10, c = e & 1023;
    float4 x = *(const float4*)(src + (long)r * cols_src + col0 + c);
    float a[4] = {x.x, x.y, x.z, x.w};
    uint32_t hp[2], lp[2];
    #pragma unroll
    for (int p = 0; p < 2; p++) {
        __half h0 = __float2half_rn(a[2*p]);
        __half h1 = __float2half_rn(a[2*p+1]);
        hp[p] = ((uint32_t)__half_as_ushort(h1) << 16) | __half_as_ushort(h0);
        lp[p] = pack_f16x2((a[2*p]   - __half2float(h0)) * 2048.f,
                           (a[2*p+1] - __half2float(h1)) * 2048.f);
    }
    ((uint2*)hi)[i] = make_uint2(hp[0], hp[1]);
    ((uint2*)lo)[i] = make_uint2(lp[0], lp[1]);
}

__global__ void split_b16(const float* __restrict__ src,
                          __nv_bfloat16* __restrict__ hi,
                          __nv_bfloat16* __restrict__ lo, int n4)
{
    int i = blockIdx.x * blockDim.x + threadIdx.x;
    if (i >= n4) return;
    float4 x = ((const float4*)src)[i];
    uint2 h, l;
    h.x = pack_bf16x2(x.x, x.y);
    h.y = pack_bf16x2(x.z, x.w);
    l.x = pack_bf16x2(x.x - __uint_as_float(h.x << 16),
                      x.y - __uint_as_float(h.x & 0xFFFF0000u));
    l.y = pack_bf16x2(x.z - __uint_as_float(h.y << 16),
                      x.w - __uint_as_float(h.y & 0xFFFF0000u));
    ((uint2*)hi)[i] = h;
    ((uint2*)lo)[i] = l;
}

__global__ void split_b16_slice(const float* __restrict__ src,
                                __nv_bfloat16* __restrict__ hi,
                                __nv_bfloat16* __restrict__ lo,
                                int cols_src, int col0)
{
    int i = blockIdx.x * blockDim.x + threadIdx.x;
    if (i >= DMODEL * INNER / 4) return;
    int e = i * 4;
    int r = e >> 10, c = e & 1023;
    float4 x = *(const float4*)(src + (long)r * cols_src + col0 + c);
    uint2 h, l;
    h.x = pack_bf16x2(x.x, x.y);
    h.y = pack_bf16x2(x.z, x.w);
    l.x = pack_bf16x2(x.x - __uint_as_float(h.x << 16),
                      x.y - __uint_as_float(h.x & 0xFFFF0000u));
    l.y = pack_bf16x2(x.z - __uint_as_float(h.y << 16),
                      x.w - __uint_as_float(h.y & 0xFFFF0000u));
    ((uint2*)hi)[i] = h;
    ((uint2*)lo)[i] = l;
}

// ===========================================================================
// Shared 16-bit GEMM skeleton: tile 128x128, chunk 32, 256 thr, 2-deep
// cp.async pipeline. launch_bounds (256,1) — R14 showed reg caps cause
// spills that cost more than occupancy buys.
// ===========================================================================
#define P16_AHI  0
#define P16_ALO  10240          // 128*40*2
#define P16_BHI  20480
#define P16_BLO  29184          // + 32*136*2
#define P16_STAGE 37888
#define P16_SMEM (2*P16_STAGE)  // 75776

// ---- fp16 3-term (dual accumulator: S = acc1 + acc2/2048) ----
__global__ __launch_bounds__(256, 1)
void gemm_fp16_ps(const __half* __restrict__ Ah, const __half* __restrict__ Al,
                  const __half* __restrict__ Bh, const __half* __restrict__ Bl,
                  float* __restrict__ C, int mode,
                  __half* __restrict__ PH, __half* __restrict__ PL)
{
    extern __shared__ char smem[];
    const uint32_t sbase = (uint32_t)__cvta_generic_to_shared(smem);

    const int tid = threadIdx.x;
    const int wid = tid >> 5;
    const int lane = tid & 31;
    const int row_a = lane >> 2;
    const int colc  = lane & 3;
    const int lm_k = lane & 15;
    const int lm_d = (lane >> 4) * 8;
    const int m0  = (wid >> 1) * 32;
    const int n0w = (wid & 1) * 64;
    const int rowBase = blockIdx.y * 128;
    const int colBase = blockIdx.x * 128;

    auto load_stage = [&](int stg, int kc) {
        const uint32_t sb = sbase + (uint32_t)(stg * P16_STAGE);
        const long ka = (long)kc * 32;
        #pragma unroll
        for (int p = 0; p < 2; p++) {
            int idx = tid + p * 256;
            int r = idx >> 2, c = (idx & 3) << 3;
            long ga = (long)(rowBase + r) * 1024 + ka + c;
            uint32_t da = (uint32_t)(r * 80 + c * 2);
            cp_async16(sb + P16_AHI + da, Ah + ga);
            cp_async16(sb + P16_ALO + da, Al + ga);
            int rb = idx >> 4, cb = (idx & 15) << 3;
            long gb = (ka + rb) * 1024 + colBase + cb;
            uint32_t db = (uint32_t)(rb * 272 + cb * 2);
            cp_async16(sb + P16_BHI + db, Bh + gb);
            cp_async16(sb + P16_BLO + db, Bl + gb);
        }
    };

    load_stage(0, 0);
    cp_async_commit();

    float ac1[2][8][4], ac2[2][8][4];
    #pragma unroll
    for (int m = 0; m < 2; m++)
        #pragma unroll
        for (int j = 0; j < 8; j++)
            #pragma unroll
            for (int c = 0; c < 4; c++) { ac1[m][j][c] = 0.f; ac2[m][j][c] = 0.f; }

    for (int kc = 0; kc < 32; kc++) {
        if (kc + 1 < 32) {
            load_stage((kc + 1) & 1, kc + 1);
            cp_async_commit();
            cp_async_wait1();
        } else {
            cp_async_wait0();
        }
        __syncthreads();

        const char* buf = smem + (kc & 1) * P16_STAGE;
        const __half* Ahi = (const __half*)(buf + P16_AHI);
        const __half* Alo = (const __half*)(buf + P16_ALO);
        const uint32_t bhi_base = sbase + (uint32_t)((kc & 1) * P16_STAGE) + P16_BHI;
        const uint32_t blo_base = sbase + (uint32_t)((kc & 1) * P16_STAGE) + P16_BLO;

        #pragma unroll
        for (int s = 0; s < 2; s++) {
            const int kb = s * 16;
            uint32_t ah0[4], as0[4], ah1[4], as1[4];
            #pragma unroll
            for (int i = 0; i < 4; i++) {
                int rr = m0 + row_a + ((i & 1) << 3);
                int kk = kb + 2 * colc + ((i >> 1) << 3);
                ah0[i] = *(const uint32_t*)&Ahi[rr * 40 + kk];
                as0[i] = *(const uint32_t*)&Alo[rr * 40 + kk];
                ah1[i] = *(const uint32_t*)&Ahi[(rr + 16) * 40 + kk];
                as1[i] = *(const uint32_t*)&Alo[(rr + 16) * 40 + kk];
            }
            #pragma unroll
            for (int j2 = 0; j2 < 4; j2++) {
                uint32_t off =
                    (uint32_t)(((kb + lm_k) * 136 + n0w + j2 * 16 + lm_d) * 2);
                uint32_t h0, h1, h2, h3, l0, l1, l2, l3;
                ldmx4t(h0, h1, h2, h3, bhi_base + off);
                ldmx4t(l0, l1, l2, l3, blo_base + off);
                int jn = j2 * 2;
                mma_fp16(ac1[0][jn], ah0, h0, h1);
                mma_fp16(ac2[0][jn], as0, h0, h1);
                mma_fp16(ac2[0][jn], ah0, l0, l1);
                mma_fp16(ac1[1][jn], ah1, h0, h1);
                mma_fp16(ac2[1][jn], as1, h0, h1);
                mma_fp16(ac2[1][jn], ah1, l0, l1);
                mma_fp16(ac1[0][jn+1], ah0, h2, h3);
                mma_fp16(ac2[0][jn+1], as0, h2, h3);
                mma_fp16(ac2[0][jn+1], ah0, l2, l3);
                mma_fp16(ac1[1][jn+1], ah1, h2, h3);
                mma_fp16(ac2[1][jn+1], as1, h2, h3);
                mma_fp16(ac2[1][jn+1], ah1, l2, l3);
            }
        }
        __syncthreads();
    }

    #pragma unroll
    for (int j = 0; j < 8; j++) {
        int col = colBase + n0w + j * 8 + 2 * colc;
        #pragma unroll
        for (int m = 0; m < 2; m++) {
            int row0 = rowBase + m0 + m * 16 + row_a;
            float v00 = fmaf(ac2[m][j][0], INV2048, ac1[m][j][0]);
            float v01 = fmaf(ac2[m][j][1], INV2048, ac1[m][j][1]);
            float v10 = fmaf(ac2[m][j][2], INV2048, ac1[m][j][2]);
            float v11 = fmaf(ac2[m][j][3], INV2048, ac1[m][j][3]);
            if (mode == 0) {
                *(float2*)(C + (long)row0 * 1024 + col) = make_float2(v00, v01);
                *(float2*)(C + (long)(row0 + 8) * 1024 + col) = make_float2(v10, v11);
            } else {
                int h = col >> 6, d = col & 63;
                #pragma unroll
                for (int rr = 0; rr < 2; rr++) {
                    int row = row0 + rr * 8;
                    float va = rr ? v10 : v00;
                    float vb = rr ? v11 : v01;
                    int bb = row >> 11, key = row & 2047;
                    long o = (((long)(bb * HEADS + h) * SEQ + key) << 6) + d;
                    __half h0 = __float2half_rn(va);
                    __half h1 = __float2half_rn(vb);
                    *(uint32_t*)(PH + o) =
                        ((uint32_t)__half_as_ushort(h1) << 16) | __half_as_ushort(h0);
                    *(uint32_t*)(PL + o) =
                        pack_f16x2((va - __half2float(h0)) * 2048.f,
                                   (vb - __half2float(h1)) * 2048.f);
                }
            }
        }
    }
}

// ---- bf16 3-term ----
__global__ __launch_bounds__(256, 1)
void gemm_bf16_ps(const __nv_bfloat16* __restrict__ Ah,
                  const __nv_bfloat16* __restrict__ Al,
                  const __nv_bfloat16* __restrict__ Bh,
                  const __nv_bfloat16* __restrict__ Bl,
                  float* __restrict__ C, const float* __restrict__ bias,
                  int mode,
                  __nv_bfloat16* __restrict__ PH, __nv_bfloat16* __restrict__ PL)
{
    extern __shared__ char smem[];
    const uint32_t sbase = (uint32_t)__cvta_generic_to_shared(smem);

    const int tid = threadIdx.x;
    const int wid = tid >> 5;
    const int lane = tid & 31;
    const int row_a = lane >> 2;
    const int colc  = lane & 3;
    const int lm_k = lane & 15;
    const int lm_d = (lane >> 4) * 8;
    const int m0  = (wid >> 1) * 32;
    const int n0w = (wid & 1) * 64;
    const int rowBase = blockIdx.y * 128;
    const int colBase = blockIdx.x * 128;

    auto load_stage = [&](int stg, int kc) {
        const uint32_t sb = sbase + (uint32_t)(stg * P16_STAGE);
        const long ka = (long)kc * 32;
        #pragma unroll
        for (int p = 0; p < 2; p++) {
            int idx = tid + p * 256;
            int r = idx >> 2, c = (idx & 3) << 3;
            long ga = (long)(rowBase + r) * 1024 + ka + c;
            uint32_t da = (uint32_t)(r * 80 + c * 2);
            cp_async16(sb + P16_AHI + da, Ah + ga);
            cp_async16(sb + P16_ALO + da, Al + ga);
            int rb = idx >> 4, cb = (idx & 15) << 3;
            long gb = (ka + rb) * 1024 + colBase + cb;
            uint32_t db = (uint32_t)(rb * 272 + cb * 2);
            cp_async16(sb + P16_BHI + db, Bh + gb);
            cp_async16(sb + P16_BLO + db, Bl + gb);
        }
    };

    load_stage(0, 0);
    cp_async_commit();

    float acc[2][8][4];
    #pragma unroll
    for (int m = 0; m < 2; m++)
        #pragma unroll
        for (int j = 0; j < 8; j++)
            #pragma unroll
            for (int c = 0; c < 4; c++) acc[m][j][c] = 0.f;

    for (int kc = 0; kc < 32; kc++) {
        if (kc + 1 < 32) {
            load_stage((kc + 1) & 1, kc + 1);
            cp_async_commit();
            cp_async_wait1();
        } else {
            cp_async_wait0();
        }
        __syncthreads();

        const char* buf = smem + (kc & 1) * P16_STAGE;
        const __nv_bfloat16* Ahi = (const __nv_bfloat16*)(buf + P16_AHI);
        const __nv_bfloat16* Alo = (const __nv_bfloat16*)(buf + P16_ALO);
        const uint32_t bhi_base = sbase + (uint32_t)((kc & 1) * P16_STAGE) + P16_BHI;
        const uint32_t blo_base = sbase + (uint32_t)((kc & 1) * P16_STAGE) + P16_BLO;

        #pragma unroll
        for (int s = 0; s < 2; s++) {
            const int kb = s * 16;
            uint32_t ah0[4], al0[4], ah1[4], al1[4];
            #pragma unroll
            for (int i = 0; i < 4; i++) {
                int rr = m0 + row_a + ((i & 1) << 3);
                int kk = kb + 2 * colc + ((i >> 1) << 3);
                ah0[i] = *(const uint32_t*)&Ahi[rr * 40 + kk];
                al0[i] = *(const uint32_t*)&Alo[rr * 40 + kk];
                ah1[i] = *(const uint32_t*)&Ahi[(rr + 16) * 40 + kk];
                al1[i] = *(const uint32_t*)&Alo[(rr + 16) * 40 + kk];
            }
            #pragma unroll
            for (int j2 = 0; j2 < 4; j2++) {
                uint32_t off =
                    (uint32_t)(((kb + lm_k) * 136 + n0w + j2 * 16 + lm_d) * 2);
                uint32_t h0, h1, h2, h3, l0, l1, l2, l3;
                ldmx4t(h0, h1, h2, h3, bhi_base + off);
                ldmx4t(l0, l1, l2, l3, blo_base + off);
                int jn = j2 * 2;
                mma_bf16(acc[0][jn], ah0, h0, h1);
                mma_bf16(acc[0][jn], al0, h0, h1);
                mma_bf16(acc[0][jn], ah0, l0, l1);
                mma_bf16(acc[1][jn], ah1, h0, h1);
                mma_bf16(acc[1][jn], al1, h0, h1);
                mma_bf16(acc[1][jn], ah1, l0, l1);
                mma_bf16(acc[0][jn+1], ah0, h2, h3);
                mma_bf16(acc[0][jn+1], al0, h2, h3);
                mma_bf16(acc[0][jn+1], ah0, l2, l3);
                mma_bf16(acc[1][jn+1], ah1, h2, h3);
                mma_bf16(acc[1][jn+1], al1, h2, h3);
                mma_bf16(acc[1][jn+1], ah1, l2, l3);
            }
        }
        __syncthreads();
    }

    #pragma unroll
    for (int j = 0; j < 8; j++) {
        int col = colBase + n0w + j * 8 + 2 * colc;
        float bx = (mode == 0 && bias) ? bias[col] : 0.f;
        float by = (mode == 0 && bias) ? bias[col + 1] : 0.f;
        #pragma unroll
        for (int m = 0; m < 2; m++) {
            int row0 = rowBase + m0 + m * 16 + row_a;
            if (mode == 0) {
                *(float2*)(C + (long)row0 * 1024 + col) =
                    make_float2(acc[m][j][0] + bx, acc[m][j][1] + by);
                *(float2*)(C + (long)(row0 + 8) * 1024 + col) =
                    make_float2(acc[m][j][2] + bx, acc[m][j][3] + by);
            } else {
                int h = col >> 6, d = col & 63;
                #pragma unroll
                for (int rr = 0; rr < 2; rr++) {
                    int row = row0 + rr * 8;
                    float va = acc[m][j][rr * 2 + 0];
                    float vb = acc[m][j][rr * 2 + 1];
                    int bb = row >> 11, key = row & 2047;
                    long o = (((long)(bb * HEADS + h) * SEQ + key) << 6) + d;
                    uint32_t hp = pack_bf16x2(va, vb);
                    *(uint32_t*)(PH + o) = hp;
                    *(uint32_t*)(PL + o) =
                        pack_bf16x2(va - __uint_as_float(hp << 16),
                                    vb - __uint_as_float(hp & 0xFFFF0000u));
                }
            }
        }
    }
}

// ===========================================================================
// Flash attention v4 (R13 config: launch_bounds (128,2))
// ===========================================================================
#define FB_KHI  0
#define FB_KLO  9216
#define FB_VHI  18432
#define FB_VLO  27648
#define FB_SIZE 36864
#define FLASH_SMEM (2*FB_SIZE)

__global__ __launch_bounds__(128, 2)
void flash_mma(const float* __restrict__ Q,
               const __half* __restrict__ KH, const __half* __restrict__ KL,
               const __nv_bfloat16* __restrict__ VH,
               const __nv_bfloat16* __restrict__ VL,
               const int* __restrict__ mask,
               __nv_bfloat16* __restrict__ OBH,
               __nv_bfloat16* __restrict__ OBL)
{
    extern __shared__ char smem[];
    const uint32_t sbase = (uint32_t)__cvta_generic_to_shared(smem);

    const int b  = blockIdx.z;
    const int h  = blockIdx.y;
    const int n0 = blockIdx.x * 64;

    const int tid   = threadIdx.x;
    const int wid   = tid >> 5;
    const int lane  = tid & 31;
    const int r0    = wid * 16;
    const int row_a = lane >> 2;
    const int colc  = lane & 3;

    const long baseQ  = (long)b * SEQ * DMODEL + (long)h * DHEAD;
    const long baseKV = ((long)(b * HEADS + h) * SEQ) << 6;

    const int lmn_key = ((lane >> 4) << 3) + (lane & 7);
    const int lmn_d   = ((lane >> 3) & 1) << 3;
    const int lmt_k   = lane & 15;
    const int lmt_d   = (lane >> 4) * 8;

    #pragma unroll
    for (int p = 0; p < 4; p++) {
        int idx = tid + p * 128;
        int r = idx >> 3, c8 = (idx & 7) << 3;
        uint32_t doff = (uint32_t)((r * 72 + c8) << 1);
        long go = baseKV + (r << 6) + c8;
        cp_async16(sbase + FB_KHI + doff, KH + go);
        cp_async16(sbase + FB_KLO + doff, KL + go);
        cp_async16(sbase + FB_VHI + doff, VH + go);
        cp_async16(sbase + FB_VLO + doff, VL + go);
    }
    cp_async_commit();

    uint32_t qh[4][4], qls[4][4];
    #pragma unroll
    for (int s = 0; s < 4; s++) {
        #pragma unroll
        for (int i = 0; i < 4; i++) {
            int rr = n0 + r0 + row_a + ((i & 1) << 3);
            int kb = (s << 4) + 2 * colc + ((i >> 1) << 3);
            float q0 = Q[baseQ + (long)rr * DMODEL + kb];
            float q1 = Q[baseQ + (long)rr * DMODEL + kb + 1];
            __half h0 = __float2half_rn(q0);
            __half h1 = __float2half_rn(q1);
            qh[s][i] = ((uint32_t)__half_as_ushort(h1) << 16) | __half_as_ushort(h0);
            qls[s][i] = pack_f16x2((q0 - __half2float(h0)) * 2048.f,
                                   (q1 - __half2float(h1)) * 2048.f);
        }
    }

    const float pen0 = (1.0f - (float)mask[b*SEQ + n0 + r0 + row_a])     * MASK_NEG;
    const float pen1 = (1.0f - (float)mask[b*SEQ + n0 + r0 + row_a + 8]) * MASK_NEG;

    float Oacc[32];
    #pragma unroll
    for (int i = 0; i < 32; i++) Oacc[i] = 0.f;
    float mstat[2] = {-1e30f, -1e30f};
    float lstat[2] = {0.f, 0.f};

    for (int kt = 0; kt < SEQ / 64; kt++) {
        cp_async_wait0();
        __syncthreads();
        const uint32_t buf = sbase + (uint32_t)((kt & 1) * FB_SIZE);

        if (kt + 1 < SEQ / 64) {
            const uint32_t nbuf = sbase + (uint32_t)(((kt + 1) & 1) * FB_SIZE);
            const long gb = baseKV + ((long)(kt + 1) << 12);
            #pragma unroll
            for (int p = 0; p < 4; p++) {
                int idx = tid + p * 128;
                int r = idx >> 3, c8 = (idx & 7) << 3;
                uint32_t doff = (uint32_t)((r * 72 + c8) << 1);
                long go = gb + (r << 6) + c8;
                cp_async16(nbuf + FB_KHI + doff, KH + go);
                cp_async16(nbuf + FB_KLO + doff, KL + go);
                cp_async16(nbuf + FB_VHI + doff, VH + go);
                cp_async16(nbuf + FB_VLO + doff, VL + go);
            }
            cp_async_commit();
        }

        float S1[32], S2[32];
        #pragma unroll
        for (int i = 0; i < 32; i++) { S1[i] = 0.f; S2[i] = 0.f; }

        const uint32_t khi_b = buf + FB_KHI;
        const uint32_t klo_b = buf + FB_KLO;
        #pragma unroll
        for (int s = 0; s < 4; s++) {
            #pragma unroll
            for (int jk = 0; jk < 4; jk++) {
                uint32_t off = (uint32_t)((((jk << 4) + lmn_key) * 72
                                           + (s << 4) + lmn_d) << 1);
                uint32_t h0, h1, h2, h3, l0, l1, l2, l3;
                ldmx4(h0, h1, h2, h3, khi_b + off);
                ldmx4(l0, l1, l2, l3, klo_b + off);
                int j0 = jk * 2;
                mma_fp16(&S1[j0*4], qh[s],  h0, h1);
                mma_fp16(&S2[j0*4], qls[s], h0, h1);
                mma_fp16(&S2[j0*4], qh[s],  l0, l1);
                mma_fp16(&S1[(j0+1)*4], qh[s],  h2, h3);
                mma_fp16(&S2[(j0+1)*4], qls[s], h2, h3);
                mma_fp16(&S2[(j0+1)*4], qh[s],  l2, l3);
            }
        }

        #pragma unroll
        for (int i = 0; i < 32; i++)
            S1[i] = fmaf(S2[i], INV2048, S1[i]);

        #pragma unroll
        for (int t = 0; t < 2; t++) {
            float pent = t ? pen1 : pen0;
            float mloc = -1e30f;
            #pragma unroll
            for (int j = 0; j < 8; j++) {
                float v0 = S1[j*4 + 2*t]     * ATT_SCALE - pent;
                float v1 = S1[j*4 + 2*t + 1] * ATT_SCALE - pent;
                S1[j*4 + 2*t]     = v0;
                S1[j*4 + 2*t + 1] = v1;
                mloc = fmaxf(mloc, fmaxf(v0, v1));
            }
            mloc = fmaxf(mloc, __shfl_xor_sync(0xffffffffu, mloc, 1));
            mloc = fmaxf(mloc, __shfl_xor_sync(0xffffffffu, mloc, 2));
            float mnew  = fmaxf(mstat[t], mloc);
            float alpha = __expf(mstat[t] - mnew);
            float lloc = 0.f;
            #pragma unroll
            for (int j = 0; j < 8; j++) {
                float p0 = __expf(S1[j*4 + 2*t]     - mnew);
                float p1 = __expf(S1[j*4 + 2*t + 1] - mnew);
                S1[j*4 + 2*t]     = p0;
                S1[j*4 + 2*t + 1] = p1;
                lloc += p0 + p1;
            }
            lloc += __shfl_xor_sync(0xffffffffu, lloc, 1);
            lloc += __shfl_xor_sync(0xffffffffu, lloc, 2);
            lstat[t] = lstat[t] * alpha + lloc;
            mstat[t] = mnew;
            #pragma unroll
            for (int j = 0; j < 8; j++) {
                Oacc[j*4 + 2*t]     *= alpha;
                Oacc[j*4 + 2*t + 1] *= alpha;
            }
        }

        const uint32_t vhi_b = buf + FB_VHI;
        const uint32_t vlo_b = buf + FB_VLO;
        #pragma unroll
        for (int t2 = 0; t2 < 4; t2++) {
            uint32_t ah[4], al[4];
            #pragma unroll
            for (int i = 0; i < 4; i++) {
                int jt  = 2*t2 + (i >> 1);
                int off = (i & 1) * 2;
                float p0 = S1[jt*4 + off];
                float p1 = S1[jt*4 + off + 1];
                uint32_t hh = pack_bf16x2(p0, p1);
                ah[i] = hh;
                al[i] = pack_bf16x2(p0 - __uint_as_float(hh << 16),
                                    p1 - __uint_as_float(hh & 0xFFFF0000u));
            }
            const uint32_t row_off =
                (uint32_t)(((t2 * 16 + lmt_k) * 72 + lmt_d) * 2);
            #pragma unroll
            for (int j2 = 0; j2 < 4; j2++) {
                uint32_t off = row_off + (uint32_t)(j2 * 16 * 2);
                uint32_t h0, h1, h2, h3, l0, l1, l2, l3;
                ldmx4t(h0, h1, h2, h3, vhi_b + off);
                ldmx4t(l0, l1, l2, l3, vlo_b + off);
                mma_bf16(&Oacc[(2*j2)*4], ah, h0, h1);
                mma_bf16(&Oacc[(2*j2)*4], al, h0, h1);
                mma_bf16(&Oacc[(2*j2)*4], ah, l0, l1);
                mma_bf16(&Oacc[(2*j2+1)*4], ah, h2, h3);
                mma_bf16(&Oacc[(2*j2+1)*4], al, h2, h3);
                mma_bf16(&Oacc[(2*j2+1)*4], ah, l2, l3);
            }
        }
    }

    float inv0 = 1.f / lstat[0];
    float inv1 = 1.f / lstat[1];
    int rowg = n0 + r0 + row_a;
    #pragma unroll
    for (int j = 0; j < 8; j++) {
        int col = (h << 6) + j * 8 + 2 * colc;
        float a0 = Oacc[j*4 + 0] * inv0, a1 = Oacc[j*4 + 1] * inv0;
        float b0 = Oacc[j*4 + 2] * inv1, b1 = Oacc[j*4 + 3] * inv1;
        long r1o = ((long)b * SEQ + rowg) * 1024 + col;
        long r2o = ((long)b * SEQ + rowg + 8) * 1024 + col;
        uint32_t h1p = pack_bf16x2(a0, a1);
        uint32_t h2p = pack_bf16x2(b0, b1);
        *(uint32_t*)(OBH + r1o) = h1p;
        *(uint32_t*)(OBH + r2o) = h2p;
        *(uint32_t*)(OBL + r1o) =
            pack_bf16x2(a0 - __uint_as_float(h1p << 16),
                        a1 - __uint_as_float(h1p & 0xFFFF0000u));
        *(uint32_t*)(OBL + r2o) =
            pack_bf16x2(b0 - __uint_as_float(h2p << 16),
                        b1 - __uint_as_float(h2p & 0xFFFF0000u));
    }
}

// ---------------------------------------------------------------------------
// Launch — parallel graph branches via event fork/join.
// Streams/events created once on the first (uncaptured) correctness call.
// ---------------------------------------------------------------------------
extern "C" void kernel_launch(void* const* d_in, const int* in_sizes, int n_in,
                              void* d_out, int out_size)
{
    const float* x       = (const float*)d_in[0];
    const float* context = (const float*)d_in[1];
    const int*   mask    = (const int*)d_in[2];
    const float* Wq      = (const float*)d_in[3];
    const float* Wkv     = (const float*)d_in[4];
    const float* Wout    = (const float*)d_in[5];
    const float* bout    = (const float*)d_in[6];
    float* out = (float*)d_out;

    float* q;
    cudaGetSymbolAddress((void**)&q, g_q);
    __half *kh, *kl;
    __nv_bfloat16 *vh, *vl;
    cudaGetSymbolAddress((void**)&kh, g_kh);
    cudaGetSymbolAddress((void**)&kl, g_kl);
    cudaGetSymbolAddress((void**)&vh, g_vh);
    cudaGetSymbolAddress((void**)&vl, g_vl);
    __half *xfh, *xfl, *ctfh, *ctfl, *wqfh, *wqfl, *wkfh, *wkfl;
    cudaGetSymbolAddress((void**)&xfh, g_xfh);
    cudaGetSymbolAddress((void**)&xfl, g_xfl);
    cudaGetSymbolAddress((void**)&ctfh, g_ctfh);
    cudaGetSymbolAddress((void**)&ctfl, g_ctfl);
    cudaGetSymbolAddress((void**)&wqfh, g_wqfh);
    cudaGetSymbolAddress((void**)&wqfl, g_wqfl);
    cudaGetSymbolAddress((void**)&wkfh, g_wkfh);
    cudaGetSymbolAddress((void**)&wkfl, g_wkfl);
    __nv_bfloat16 *ctbh, *ctbl, *wvbh, *wvbl, *wobh, *wobl, *obh, *obl;
    cudaGetSymbolAddress((void**)&ctbh, g_ctbh);
    cudaGetSymbolAddress((void**)&ctbl, g_ctbl);
    cudaGetSymbolAddress((void**)&wvbh, g_wvbh);
    cudaGetSymbolAddress((void**)&wvbl, g_wvbl);
    cudaGetSymbolAddress((void**)&wobh, g_wobh);
    cudaGetSymbolAddress((void**)&wobl, g_wobl);
    cudaGetSymbolAddress((void**)&obh, g_obh);
    cudaGetSymbolAddress((void**)&obl, g_obl);

    static cudaStream_t s1 = nullptr, s2 = nullptr;
    static cudaEvent_t  e0 = nullptr, e1 = nullptr, e2 = nullptr;
    if (!s1) {
        cudaStreamCreateWithFlags(&s1, cudaStreamNonBlocking);
        cudaStreamCreateWithFlags(&s2, cudaStreamNonBlocking);
        cudaEventCreateWithFlags(&e0, cudaEventDisableTiming);
        cudaEventCreateWithFlags(&e1, cudaEventDisableTiming);
        cudaEventCreateWithFlags(&e2, cudaEventDisableTiming);
        cudaFuncSetAttribute(flash_mma,
                             cudaFuncAttributeMaxDynamicSharedMemorySize, FLASH_SMEM);
        cudaFuncSetAttribute(gemm_fp16_ps,
                             cudaFuncAttributeMaxDynamicSharedMemorySize, P16_SMEM);
        cudaFuncSetAttribute(gemm_bf16_ps,
                             cudaFuncAttributeMaxDynamicSharedMemorySize, P16_SMEM);
    }

    const int nact4 = ROWS * DMODEL / 4;
    const int nw4   = DMODEL * INNER / 4;
    dim3 gg(1024 / 128, 4096 / 128);
    dim3 grid_attn(SEQ / 64, HEADS, BATCH);

    // ---- fork ----
    cudaEventRecord(e0, 0);
    cudaStreamWaitEvent(s1, e0, 0);
    cudaStreamWaitEvent(s2, e0, 0);

    // main: q path
    split_f16<<<nact4 / 256, 256, 0, 0>>>(x, xfh, xfl, nact4);
    split_f16<<<nw4 / 256, 256, 0, 0>>>(Wq, wqfh, wqfl, nw4);
    gemm_fp16_ps<<<gg, 256, P16_SMEM, 0>>>(xfh, xfl, wqfh, wqfl, q, 0, nullptr, nullptr);

    // s1: k path (emits per-head fp16 hi/lo directly)
    split_f16<<<nact4 / 256, 256, 0, s1>>>(context, ctfh, ctfl, nact4);
    split_f16_slice<<<nw4 / 256, 256, 0, s1>>>(Wkv, wkfh, wkfl, 2 * INNER, 0);
    gemm_fp16_ps<<<gg, 256, P16_SMEM, s1>>>(ctfh, ctfl, wkfh, wkfl, nullptr, 1, kh, kl);

    // s2: v path (emits per-head bf16 hi/lo directly) + Wout split
    split_b16<<<nact4 / 256, 256, 0, s2>>>(context, ctbh, ctbl, nact4);
    split_b16_slice<<<nw4 / 256, 256, 0, s2>>>(Wkv, wvbh, wvbl, 2 * INNER, INNER);
    split_b16<<<nw4 / 256, 256, 0, s2>>>(Wout, wobh, wobl, nw4);
    gemm_bf16_ps<<<gg, 256, P16_SMEM, s2>>>(ctbh, ctbl, wvbh, wvbl, nullptr, nullptr, 2, vh, vl);

    // ---- join ----
    cudaEventRecord(e1, s1);
    cudaEventRecord(e2, s2);
    cudaStreamWaitEvent(0, e1, 0);
    cudaStreamWaitEvent(0, e2, 0);

    // attention + output projection (serial tail)
    flash_mma<<<grid_attn, 128, FLASH_SMEM, 0>>>(q, kh, kl, vh, vl, mask, obh, obl);
    gemm_bf16_ps<<<gg, 256, P16_SMEM, 0>>>(obh, obl, wobh, wobl, out, bout, 0, nullptr, nullptr);
}

// round 17
// speedup vs baseline: 1.5361x; 1.5361x over previous
#include <cuda_runtime.h>
#include <cuda_bf16.h>
#include <cuda_fp16.h>
#include <math.h>
#include <stdint.h>

// Problem constants
#define BATCH   2
#define SEQ     2048
#define DMODEL  1024
#define HEADS   16
#define DHEAD   64
#define INNER   (HEADS*DHEAD)      // 1024
#define ROWS    (BATCH*SEQ)        // 4096
#define ATT_SCALE 0.125f
#define MASK_NEG 1000000.0f
#define INV2048 4.8828125e-4f

// ---------------------------------------------------------------------------
// Scratch (allocation-free rule: static __device__ globals)
// ---------------------------------------------------------------------------
__device__ float g_q[ROWS*INNER];
// flash K/V operands, per-head layout [b][h][key][64]
__device__ __half        g_kh[ROWS*INNER];
__device__ __half        g_kl[ROWS*INNER];   // (k - hi) * 2048
__device__ __nv_bfloat16 g_vh[ROWS*INNER];
__device__ __nv_bfloat16 g_vl[ROWS*INNER];
// pre-split GEMM operands (fp16: lo scaled by 2048)
__device__ __half g_xfh[ROWS*DMODEL],  g_xfl[ROWS*DMODEL];
__device__ __half g_ctfh[ROWS*DMODEL], g_ctfl[ROWS*DMODEL];
__device__ __half g_wqfh[DMODEL*INNER], g_wqfl[DMODEL*INNER];
__device__ __half g_wkfh[DMODEL*INNER], g_wkfl[DMODEL*INNER];
__device__ __nv_bfloat16 g_ctbh[ROWS*DMODEL], g_ctbl[ROWS*DMODEL];
__device__ __nv_bfloat16 g_wvbh[DMODEL*INNER], g_wvbl[DMODEL*INNER];
__device__ __nv_bfloat16 g_wobh[INNER*DMODEL], g_wobl[INNER*DMODEL];
__device__ __nv_bfloat16 g_obh[ROWS*INNER], g_obl[ROWS*INNER];

// ---------------------------------------------------------------------------
// mma.sync / ldmatrix / cp.async helpers (compute_103-compatible; NO tcgen05)
// ---------------------------------------------------------------------------
__device__ __forceinline__ void mma_bf16(float* d, const uint32_t* a,
                                         uint32_t b0, uint32_t b1)
{
    asm volatile(
        "mma.sync.aligned.m16n8k16.row.col.f32.bf16.bf16.f32 "
        "{%0,%1,%2,%3}, {%4,%5,%6,%7}, {%8,%9}, {%0,%1,%2,%3};"
        : "+f"(d[0]), "+f"(d[1]), "+f"(d[2]), "+f"(d[3])
        : "r"(a[0]), "r"(a[1]), "r"(a[2]), "r"(a[3]), "r"(b0), "r"(b1));
}

__device__ __forceinline__ void mma_fp16(float* d, const uint32_t* a,
                                         uint32_t b0, uint32_t b1)
{
    asm volatile(
        "mma.sync.aligned.m16n8k16.row.col.f32.f16.f16.f32 "
        "{%0,%1,%2,%3}, {%4,%5,%6,%7}, {%8,%9}, {%0,%1,%2,%3};"
        : "+f"(d[0]), "+f"(d[1]), "+f"(d[2]), "+f"(d[3])
        : "r"(a[0]), "r"(a[1]), "r"(a[2]), "r"(a[3]), "r"(b0), "r"(b1));
}

__device__ __forceinline__ uint32_t pack_bf16x2(float lo_val, float hi_val) {
    uint32_t r;
    asm("cvt.rn.bf16x2.f32 %0, %1, %2;" : "=r"(r) : "f"(hi_val), "f"(lo_val));
    return r;
}

__device__ __forceinline__ uint32_t pack_f16x2(float lo_val, float hi_val) {
    __half h0 = __float2half_rn(lo_val);
    __half h1 = __float2half_rn(hi_val);
    return ((uint32_t)__half_as_ushort(h1) << 16) | __half_as_ushort(h0);
}

__device__ __forceinline__ void ldmx4t(uint32_t& r0, uint32_t& r1,
                                       uint32_t& r2, uint32_t& r3, uint32_t addr)
{
    asm volatile(
        "ldmatrix.sync.aligned.m8n8.x4.trans.shared.b16 {%0,%1,%2,%3}, [%4];"
        : "=r"(r0), "=r"(r1), "=r"(r2), "=r"(r3) : "r"(addr));
}
__device__ __forceinline__ void ldmx4(uint32_t& r0, uint32_t& r1,
                                      uint32_t& r2, uint32_t& r3, uint32_t addr)
{
    asm volatile(
        "ldmatrix.sync.aligned.m8n8.x4.shared.b16 {%0,%1,%2,%3}, [%4];"
        : "=r"(r0), "=r"(r1), "=r"(r2), "=r"(r3) : "r"(addr));
}

__device__ __forceinline__ void cp_async16(uint32_t saddr, const void* gptr) {
    asm volatile("cp.async.cg.shared.global [%0], [%1], 16;"
                 :: "r"(saddr), "l"(gptr));
}
__device__ __forceinline__ void cp_async_commit() {
    asm volatile("cp.async.commit_group;");
}
__device__ __forceinline__ void cp_async_wait0() {
    asm volatile("cp.async.wait_group 0;");
}
__device__ __forceinline__ void cp_async_wait1() {
    asm volatile("cp.async.wait_group 1;");
}

// ===========================================================================
// Fused one-shot operand split kernel. Task ranges (in float4 chunks):
//   [0, NACT)        : x -> xfh/xfl (fp16 hi, lo*2048)
//   [NACT, 2*NACT)   : context -> ctfh/ctfl AND ctbh/ctbl (one read)
//   [2*NACT, +NW)    : Wq -> wqfh/wqfl
//   [.., +NW)        : Wkv[:, :1024] -> wkfh/wkfl
//   [.., +NW)        : Wkv[:, 1024:] -> wvbh/wvbl (bf16)
//   [.., +NW)        : Wout -> wobh/wobl (bf16)
// Rounding identical to R13's individual split kernels.
// ===========================================================================
#define NACT (ROWS*DMODEL/4)     // 1,048,576
#define NW   (DMODEL*INNER/4)    // 262,144

__device__ __forceinline__ void split4_f16(float4 x, uint2& hp, uint2& lp) {
    float a[4] = {x.x, x.y, x.z, x.w};
    uint32_t h[2], l[2];
    #pragma unroll
    for (int p = 0; p < 2; p++) {
        __half h0 = __float2half_rn(a[2*p]);
        __half h1 = __float2half_rn(a[2*p+1]);
        h[p] = ((uint32_t)__half_as_ushort(h1) << 16) | __half_as_ushort(h0);
        l[p] = pack_f16x2((a[2*p]   - __half2float(h0)) * 2048.f,
                          (a[2*p+1] - __half2float(h1)) * 2048.f);
    }
    hp = make_uint2(h[0], h[1]);
    lp = make_uint2(l[0], l[1]);
}

__device__ __forceinline__ void split4_b16(float4 x, uint2& hp, uint2& lp) {
    hp.x = pack_bf16x2(x.x, x.y);
    hp.y = pack_bf16x2(x.z, x.w);
    lp.x = pack_bf16x2(x.x - __uint_as_float(hp.x << 16),
                       x.y - __uint_as_float(hp.x & 0xFFFF0000u));
    lp.y = pack_bf16x2(x.z - __uint_as_float(hp.y << 16),
                       x.w - __uint_as_float(hp.y & 0xFFFF0000u));
}

__global__ void fused_split(const float* __restrict__ x,
                            const float* __restrict__ context,
                            const float* __restrict__ Wq,
                            const float* __restrict__ Wkv,
                            const float* __restrict__ Wout,
                            __half* __restrict__ xfh, __half* __restrict__ xfl,
                            __half* __restrict__ ctfh, __half* __restrict__ ctfl,
                            __nv_bfloat16* __restrict__ ctbh, __nv_bfloat16* __restrict__ ctbl,
                            __half* __restrict__ wqfh, __half* __restrict__ wqfl,
                            __half* __restrict__ wkfh, __half* __restrict__ wkfl,
                            __nv_bfloat16* __restrict__ wvbh, __nv_bfloat16* __restrict__ wvbl,
                            __nv_bfloat16* __restrict__ wobh, __nv_bfloat16* __restrict__ wobl)
{
    int i = blockIdx.x * blockDim.x + threadIdx.x;
    uint2 hp, lp;
    if (i < NACT) {
        float4 v = ((const float4*)x)[i];
        split4_f16(v, hp, lp);
        ((uint2*)xfh)[i] = hp; ((uint2*)xfl)[i] = lp;
    } else if (i < 2 * NACT) {
        int j = i - NACT;
        float4 v = ((const float4*)context)[j];
        split4_f16(v, hp, lp);
        ((uint2*)ctfh)[j] = hp; ((uint2*)ctfl)[j] = lp;
        split4_b16(v, hp, lp);
        ((uint2*)ctbh)[j] = hp; ((uint2*)ctbl)[j] = lp;
    } else if (i < 2 * NACT + NW) {
        int j = i - 2 * NACT;
        float4 v = ((const float4*)Wq)[j];
        split4_f16(v, hp, lp);
        ((uint2*)wqfh)[j] = hp; ((uint2*)wqfl)[j] = lp;
    } else if (i < 2 * NACT + 2 * NW) {
        int j = i - (2 * NACT + NW);
        int e = j * 4;
        int r = e >> 10, c = e & 1023;
        float4 v = *(const float4*)(Wkv + (long)r * (2 * INNER) + c);
        split4_f16(v, hp, lp);
        ((uint2*)wkfh)[j] = hp; ((uint2*)wkfl)[j] = lp;
    } else if (i < 2 * NACT + 3 * NW) {
        int j = i - (2 * NACT + 2 * NW);
        int e = j * 4;
        int r = e >> 10, c = e & 1023;
        float4 v = *(const float4*)(Wkv + (long)r * (2 * INNER) + INNER + c);
        split4_b16(v, hp, lp);
        ((uint2*)wvbh)[j] = hp; ((uint2*)wvbl)[j] = lp;
    } else if (i < 2 * NACT + 4 * NW) {
        int j = i - (2 * NACT + 3 * NW);
        float4 v = ((const float4*)Wout)[j];
        split4_b16(v, hp, lp);
        ((uint2*)wobh)[j] = hp; ((uint2*)wobl)[j] = lp;
    }
}
#define SPLIT_TASKS (2*NACT + 4*NW)

// ===========================================================================
// Shared 16-bit GEMM skeleton: tile 128x128, chunk 32, 256 thr, 2-deep
// cp.async pipeline, 1 CTA/SM (R14: reg caps cause spills).
// ===========================================================================
#define P16_AHI  0
#define P16_ALO  10240          // 128*40*2
#define P16_BHI  20480
#define P16_BLO  29184          // + 32*136*2
#define P16_STAGE 37888
#define P16_SMEM (2*P16_STAGE)  // 75776

// ---- fp16 3-term, q and k problems merged on gridDim.z ----
// z=0: C = A0*B0 (fp32, q). z=1: A1*B1 -> PH/PL fp16 hi/lo per-head (k).
__global__ __launch_bounds__(256, 1)
void gemm_fp16_qk(const __half* __restrict__ Ah0, const __half* __restrict__ Al0,
                  const __half* __restrict__ Bh0, const __half* __restrict__ Bl0,
                  float* __restrict__ C,
                  const __half* __restrict__ Ah1, const __half* __restrict__ Al1,
                  const __half* __restrict__ Bh1, const __half* __restrict__ Bl1,
                  __half* __restrict__ PH, __half* __restrict__ PL)
{
    extern __shared__ char smem[];
    const uint32_t sbase = (uint32_t)__cvta_generic_to_shared(smem);

    const int mode = blockIdx.z;
    const __half* Ah = mode ? Ah1 : Ah0;
    const __half* Al = mode ? Al1 : Al0;
    const __half* Bh = mode ? Bh1 : Bh0;
    const __half* Bl = mode ? Bl1 : Bl0;

    const int tid = threadIdx.x;
    const int wid = tid >> 5;
    const int lane = tid & 31;
    const int row_a = lane >> 2;
    const int colc  = lane & 3;
    const int lm_k = lane & 15;
    const int lm_d = (lane >> 4) * 8;
    const int m0  = (wid >> 1) * 32;
    const int n0w = (wid & 1) * 64;
    const int rowBase = blockIdx.y * 128;
    const int colBase = blockIdx.x * 128;

    auto load_stage = [&](int stg, int kc) {
        const uint32_t sb = sbase + (uint32_t)(stg * P16_STAGE);
        const long ka = (long)kc * 32;
        #pragma unroll
        for (int p = 0; p < 2; p++) {
            int idx = tid + p * 256;
            int r = idx >> 2, c = (idx & 3) << 3;
            long ga = (long)(rowBase + r) * 1024 + ka + c;
            uint32_t da = (uint32_t)(r * 80 + c * 2);
            cp_async16(sb + P16_AHI + da, Ah + ga);
            cp_async16(sb + P16_ALO + da, Al + ga);
            int rb = idx >> 4, cb = (idx & 15) << 3;
            long gb = (ka + rb) * 1024 + colBase + cb;
            uint32_t db = (uint32_t)(rb * 272 + cb * 2);
            cp_async16(sb + P16_BHI + db, Bh + gb);
            cp_async16(sb + P16_BLO + db, Bl + gb);
        }
    };

    load_stage(0, 0);
    cp_async_commit();

    float ac1[2][8][4], ac2[2][8][4];
    #pragma unroll
    for (int m = 0; m < 2; m++)
        #pragma unroll
        for (int j = 0; j < 8; j++)
            #pragma unroll
            for (int c = 0; c < 4; c++) { ac1[m][j][c] = 0.f; ac2[m][j][c] = 0.f; }

    for (int kc = 0; kc < 32; kc++) {
        if (kc + 1 < 32) {
            load_stage((kc + 1) & 1, kc + 1);
            cp_async_commit();
            cp_async_wait1();
        } else {
            cp_async_wait0();
        }
        __syncthreads();

        const char* buf = smem + (kc & 1) * P16_STAGE;
        const __half* Ahi = (const __half*)(buf + P16_AHI);
        const __half* Alo = (const __half*)(buf + P16_ALO);
        const uint32_t bhi_base = sbase + (uint32_t)((kc & 1) * P16_STAGE) + P16_BHI;
        const uint32_t blo_base = sbase + (uint32_t)((kc & 1) * P16_STAGE) + P16_BLO;

        #pragma unroll
        for (int s = 0; s < 2; s++) {
            const int kb = s * 16;
            uint32_t ah0[4], as0[4], ah1[4], as1[4];
            #pragma unroll
            for (int i = 0; i < 4; i++) {
                int rr = m0 + row_a + ((i & 1) << 3);
                int kk = kb + 2 * colc + ((i >> 1) << 3);
                ah0[i] = *(const uint32_t*)&Ahi[rr * 40 + kk];
                as0[i] = *(const uint32_t*)&Alo[rr * 40 + kk];
                ah1[i] = *(const uint32_t*)&Ahi[(rr + 16) * 40 + kk];
                as1[i] = *(const uint32_t*)&Alo[(rr + 16) * 40 + kk];
            }
            #pragma unroll
            for (int j2 = 0; j2 < 4; j2++) {
                uint32_t off =
                    (uint32_t)(((kb + lm_k) * 136 + n0w + j2 * 16 + lm_d) * 2);
                uint32_t h0, h1, h2, h3, l0, l1, l2, l3;
                ldmx4t(h0, h1, h2, h3, bhi_base + off);
                ldmx4t(l0, l1, l2, l3, blo_base + off);
                int jn = j2 * 2;
                mma_fp16(ac1[0][jn], ah0, h0, h1);
                mma_fp16(ac2[0][jn], as0, h0, h1);
                mma_fp16(ac2[0][jn], ah0, l0, l1);
                mma_fp16(ac1[1][jn], ah1, h0, h1);
                mma_fp16(ac2[1][jn], as1, h0, h1);
                mma_fp16(ac2[1][jn], ah1, l0, l1);
                mma_fp16(ac1[0][jn+1], ah0, h2, h3);
                mma_fp16(ac2[0][jn+1], as0, h2, h3);
                mma_fp16(ac2[0][jn+1], ah0, l2, l3);
                mma_fp16(ac1[1][jn+1], ah1, h2, h3);
                mma_fp16(ac2[1][jn+1], as1, h2, h3);
                mma_fp16(ac2[1][jn+1], ah1, l2, l3);
            }
        }
        __syncthreads();
    }

    #pragma unroll
    for (int j = 0; j < 8; j++) {
        int col = colBase + n0w + j * 8 + 2 * colc;
        #pragma unroll
        for (int m = 0; m < 2; m++) {
            int row0 = rowBase + m0 + m * 16 + row_a;
            float v00 = fmaf(ac2[m][j][0], INV2048, ac1[m][j][0]);
            float v01 = fmaf(ac2[m][j][1], INV2048, ac1[m][j][1]);
            float v10 = fmaf(ac2[m][j][2], INV2048, ac1[m][j][2]);
            float v11 = fmaf(ac2[m][j][3], INV2048, ac1[m][j][3]);
            if (mode == 0) {
                *(float2*)(C + (long)row0 * 1024 + col) = make_float2(v00, v01);
                *(float2*)(C + (long)(row0 + 8) * 1024 + col) = make_float2(v10, v11);
            } else {
                int h = col >> 6, d = col & 63;
                #pragma unroll
                for (int rr = 0; rr < 2; rr++) {
                    int row = row0 + rr * 8;
                    float va = rr ? v10 : v00;
                    float vb = rr ? v11 : v01;
                    int bb = row >> 11, key = row & 2047;
                    long o = (((long)(bb * HEADS + h) * SEQ + key) << 6) + d;
                    __half h0 = __float2half_rn(va);
                    __half h1 = __float2half_rn(vb);
                    *(uint32_t*)(PH + o) =
                        ((uint32_t)__half_as_ushort(h1) << 16) | __half_as_ushort(h0);
                    *(uint32_t*)(PL + o) =
                        pack_f16x2((va - __half2float(h0)) * 2048.f,
                                   (vb - __half2float(h1)) * 2048.f);
                }
            }
        }
    }
}

// ---- bf16 3-term (v and out projections) ----
__global__ __launch_bounds__(256, 1)
void gemm_bf16_ps(const __nv_bfloat16* __restrict__ Ah,
                  const __nv_bfloat16* __restrict__ Al,
                  const __nv_bfloat16* __restrict__ Bh,
                  const __nv_bfloat16* __restrict__ Bl,
                  float* __restrict__ C, const float* __restrict__ bias,
                  int mode,
                  __nv_bfloat16* __restrict__ PH, __nv_bfloat16* __restrict__ PL)
{
    extern __shared__ char smem[];
    const uint32_t sbase = (uint32_t)__cvta_generic_to_shared(smem);

    const int tid = threadIdx.x;
    const int wid = tid >> 5;
    const int lane = tid & 31;
    const int row_a = lane >> 2;
    const int colc  = lane & 3;
    const int lm_k = lane & 15;
    const int lm_d = (lane >> 4) * 8;
    const int m0  = (wid >> 1) * 32;
    const int n0w = (wid & 1) * 64;
    const int rowBase = blockIdx.y * 128;
    const int colBase = blockIdx.x * 128;

    auto load_stage = [&](int stg, int kc) {
        const uint32_t sb = sbase + (uint32_t)(stg * P16_STAGE);
        const long ka = (long)kc * 32;
        #pragma unroll
        for (int p = 0; p < 2; p++) {
            int idx = tid + p * 256;
            int r = idx >> 2, c = (idx & 3) << 3;
            long ga = (long)(rowBase + r) * 1024 + ka + c;
            uint32_t da = (uint32_t)(r * 80 + c * 2);
            cp_async16(sb + P16_AHI + da, Ah + ga);
            cp_async16(sb + P16_ALO + da, Al + ga);
            int rb = idx >> 4, cb = (idx & 15) << 3;
            long gb = (ka + rb) * 1024 + colBase + cb;
            uint32_t db = (uint32_t)(rb * 272 + cb * 2);
            cp_async16(sb + P16_BHI + db, Bh + gb);
            cp_async16(sb + P16_BLO + db, Bl + gb);
        }
    };

    load_stage(0, 0);
    cp_async_commit();

    float acc[2][8][4];
    #pragma unroll
    for (int m = 0; m < 2; m++)
        #pragma unroll
        for (int j = 0; j < 8; j++)
            #pragma unroll
            for (int c = 0; c < 4; c++) acc[m][j][c] = 0.f;

    for (int kc = 0; kc < 32; kc++) {
        if (kc + 1 < 32) {
            load_stage((kc + 1) & 1, kc + 1);
            cp_async_commit();
            cp_async_wait1();
        } else {
            cp_async_wait0();
        }
        __syncthreads();

        const char* buf = smem + (kc & 1) * P16_STAGE;
        const __nv_bfloat16* Ahi = (const __nv_bfloat16*)(buf + P16_AHI);
        const __nv_bfloat16* Alo = (const __nv_bfloat16*)(buf + P16_ALO);
        const uint32_t bhi_base = sbase + (uint32_t)((kc & 1) * P16_STAGE) + P16_BHI;
        const uint32_t blo_base = sbase + (uint32_t)((kc & 1) * P16_STAGE) + P16_BLO;

        #pragma unroll
        for (int s = 0; s < 2; s++) {
            const int kb = s * 16;
            uint32_t ah0[4], al0[4], ah1[4], al1[4];
            #pragma unroll
            for (int i = 0; i < 4; i++) {
                int rr = m0 + row_a + ((i & 1) << 3);
                int kk = kb + 2 * colc + ((i >> 1) << 3);
                ah0[i] = *(const uint32_t*)&Ahi[rr * 40 + kk];
                al0[i] = *(const uint32_t*)&Alo[rr * 40 + kk];
                ah1[i] = *(const uint32_t*)&Ahi[(rr + 16) * 40 + kk];
                al1[i] = *(const uint32_t*)&Alo[(rr + 16) * 40 + kk];
            }
            #pragma unroll
            for (int j2 = 0; j2 < 4; j2++) {
                uint32_t off =
                    (uint32_t)(((kb + lm_k) * 136 + n0w + j2 * 16 + lm_d) * 2);
                uint32_t h0, h1, h2, h3, l0, l1, l2, l3;
                ldmx4t(h0, h1, h2, h3, bhi_base + off);
                ldmx4t(l0, l1, l2, l3, blo_base + off);
                int jn = j2 * 2;
                mma_bf16(acc[0][jn], ah0, h0, h1);
                mma_bf16(acc[0][jn], al0, h0, h1);
                mma_bf16(acc[0][jn], ah0, l0, l1);
                mma_bf16(acc[1][jn], ah1, h0, h1);
                mma_bf16(acc[1][jn], al1, h0, h1);
                mma_bf16(acc[1][jn], ah1, l0, l1);
                mma_bf16(acc[0][jn+1], ah0, h2, h3);
                mma_bf16(acc[0][jn+1], al0, h2, h3);
                mma_bf16(acc[0][jn+1], ah0, l2, l3);
                mma_bf16(acc[1][jn+1], ah1, h2, h3);
                mma_bf16(acc[1][jn+1], al1, h2, h3);
                mma_bf16(acc[1][jn+1], ah1, l2, l3);
            }
        }
        __syncthreads();
    }

    #pragma unroll
    for (int j = 0; j < 8; j++) {
        int col = colBase + n0w + j * 8 + 2 * colc;
        float bx = (mode == 0 && bias) ? bias[col] : 0.f;
        float by = (mode == 0 && bias) ? bias[col + 1] : 0.f;
        #pragma unroll
        for (int m = 0; m < 2; m++) {
            int row0 = rowBase + m0 + m * 16 + row_a;
            if (mode == 0) {
                *(float2*)(C + (long)row0 * 1024 + col) =
                    make_float2(acc[m][j][0] + bx, acc[m][j][1] + by);
                *(float2*)(C + (long)(row0 + 8) * 1024 + col) =
                    make_float2(acc[m][j][2] + bx, acc[m][j][3] + by);
            } else {
                int h = col >> 6, d = col & 63;
                #pragma unroll
                for (int rr = 0; rr < 2; rr++) {
                    int row = row0 + rr * 8;
                    float va = acc[m][j][rr * 2 + 0];
                    float vb = acc[m][j][rr * 2 + 1];
                    int bb = row >> 11, key = row & 2047;
                    long o = (((long)(bb * HEADS + h) * SEQ + key) << 6) + d;
                    uint32_t hp = pack_bf16x2(va, vb);
                    *(uint32_t*)(PH + o) = hp;
                    *(uint32_t*)(PL + o) =
                        pack_bf16x2(va - __uint_as_float(hp << 16),
                                    vb - __uint_as_float(hp & 0xFFFF0000u));
                }
            }
        }
    }
}

// ===========================================================================
// Flash attention v4 (R13 exact)
// ===========================================================================
#define FB_KHI  0
#define FB_KLO  9216
#define FB_VHI  18432
#define FB_VLO  27648
#define FB_SIZE 36864
#define FLASH_SMEM (2*FB_SIZE)

__global__ __launch_bounds__(128, 2)
void flash_mma(const float* __restrict__ Q,
               const __half* __restrict__ KH, const __half* __restrict__ KL,
               const __nv_bfloat16* __restrict__ VH,
               const __nv_bfloat16* __restrict__ VL,
               const int* __restrict__ mask,
               __nv_bfloat16* __restrict__ OBH,
               __nv_bfloat16* __restrict__ OBL)
{
    extern __shared__ char smem[];
    const uint32_t sbase = (uint32_t)__cvta_generic_to_shared(smem);

    const int b  = blockIdx.z;
    const int h  = blockIdx.y;
    const int n0 = blockIdx.x * 64;

    const int tid   = threadIdx.x;
    const int wid   = tid >> 5;
    const int lane  = tid & 31;
    const int r0    = wid * 16;
    const int row_a = lane >> 2;
    const int colc  = lane & 3;

    const long baseQ  = (long)b * SEQ * DMODEL + (long)h * DHEAD;
    const long baseKV = ((long)(b * HEADS + h) * SEQ) << 6;

    const int lmn_key = ((lane >> 4) << 3) + (lane & 7);
    const int lmn_d   = ((lane >> 3) & 1) << 3;
    const int lmt_k   = lane & 15;
    const int lmt_d   = (lane >> 4) * 8;

    #pragma unroll
    for (int p = 0; p < 4; p++) {
        int idx = tid + p * 128;
        int r = idx >> 3, c8 = (idx & 7) << 3;
        uint32_t doff = (uint32_t)((r * 72 + c8) << 1);
        long go = baseKV + (r << 6) + c8;
        cp_async16(sbase + FB_KHI + doff, KH + go);
        cp_async16(sbase + FB_KLO + doff, KL + go);
        cp_async16(sbase + FB_VHI + doff, VH + go);
        cp_async16(sbase + FB_VLO + doff, VL + go);
    }
    cp_async_commit();

    uint32_t qh[4][4], qls[4][4];
    #pragma unroll
    for (int s = 0; s < 4; s++) {
        #pragma unroll
        for (int i = 0; i < 4; i++) {
            int rr = n0 + r0 + row_a + ((i & 1) << 3);
            int kb = (s << 4) + 2 * colc + ((i >> 1) << 3);
            float q0 = Q[baseQ + (long)rr * DMODEL + kb];
            float q1 = Q[baseQ + (long)rr * DMODEL + kb + 1];
            __half h0 = __float2half_rn(q0);
            __half h1 = __float2half_rn(q1);
            qh[s][i] = ((uint32_t)__half_as_ushort(h1) << 16) | __half_as_ushort(h0);
            qls[s][i] = pack_f16x2((q0 - __half2float(h0)) * 2048.f,
                                   (q1 - __half2float(h1)) * 2048.f);
        }
    }

    const float pen0 = (1.0f - (float)mask[b*SEQ + n0 + r0 + row_a])     * MASK_NEG;
    const float pen1 = (1.0f - (float)mask[b*SEQ + n0 + r0 + row_a + 8]) * MASK_NEG;

    float Oacc[32];
    #pragma unroll
    for (int i = 0; i < 32; i++) Oacc[i] = 0.f;
    float mstat[2] = {-1e30f, -1e30f};
    float lstat[2] = {0.f, 0.f};

    for (int kt = 0; kt < SEQ / 64; kt++) {
        cp_async_wait0();
        __syncthreads();
        const uint32_t buf = sbase + (uint32_t)((kt & 1) * FB_SIZE);

        if (kt + 1 < SEQ / 64) {
            const uint32_t nbuf = sbase + (uint32_t)(((kt + 1) & 1) * FB_SIZE);
            const long gb = baseKV + ((long)(kt + 1) << 12);
            #pragma unroll
            for (int p = 0; p < 4; p++) {
                int idx = tid + p * 128;
                int r = idx >> 3, c8 = (idx & 7) << 3;
                uint32_t doff = (uint32_t)((r * 72 + c8) << 1);
                long go = gb + (r << 6) + c8;
                cp_async16(nbuf + FB_KHI + doff, KH + go);
                cp_async16(nbuf + FB_KLO + doff, KL + go);
                cp_async16(nbuf + FB_VHI + doff, VH + go);
                cp_async16(nbuf + FB_VLO + doff, VL + go);
            }
            cp_async_commit();
        }

        float S1[32], S2[32];
        #pragma unroll
        for (int i = 0; i < 32; i++) { S1[i] = 0.f; S2[i] = 0.f; }

        const uint32_t khi_b = buf + FB_KHI;
        const uint32_t klo_b = buf + FB_KLO;
        #pragma unroll
        for (int s = 0; s < 4; s++) {
            #pragma unroll
            for (int jk = 0; jk < 4; jk++) {
                uint32_t off = (uint32_t)((((jk << 4) + lmn_key) * 72
                                           + (s << 4) + lmn_d) << 1);
                uint32_t h0, h1, h2, h3, l0, l1, l2, l3;
                ldmx4(h0, h1, h2, h3, khi_b + off);
                ldmx4(l0, l1, l2, l3, klo_b + off);
                int j0 = jk * 2;
                mma_fp16(&S1[j0*4], qh[s],  h0, h1);
                mma_fp16(&S2[j0*4], qls[s], h0, h1);
                mma_fp16(&S2[j0*4], qh[s],  l0, l1);
                mma_fp16(&S1[(j0+1)*4], qh[s],  h2, h3);
                mma_fp16(&S2[(j0+1)*4], qls[s], h2, h3);
                mma_fp16(&S2[(j0+1)*4], qh[s],  l2, l3);
            }
        }

        #pragma unroll
        for (int i = 0; i < 32; i++)
            S1[i] = fmaf(S2[i], INV2048, S1[i]);

        #pragma unroll
        for (int t = 0; t < 2; t++) {
            float pent = t ? pen1 : pen0;
            float mloc = -1e30f;
            #pragma unroll
            for (int j = 0; j < 8; j++) {
                float v0 = S1[j*4 + 2*t]     * ATT_SCALE - pent;
                float v1 = S1[j*4 + 2*t + 1] * ATT_SCALE - pent;
                S1[j*4 + 2*t]     = v0;
                S1[j*4 + 2*t + 1] = v1;
                mloc = fmaxf(mloc, fmaxf(v0, v1));
            }
            mloc = fmaxf(mloc, __shfl_xor_sync(0xffffffffu, mloc, 1));
            mloc = fmaxf(mloc, __shfl_xor_sync(0xffffffffu, mloc, 2));
            float mnew  = fmaxf(mstat[t], mloc);
            float alpha = __expf(mstat[t] - mnew);
            float lloc = 0.f;
            #pragma unroll
            for (int j = 0; j < 8; j++) {
                float p0 = __expf(S1[j*4 + 2*t]     - mnew);
                float p1 = __expf(S1[j*4 + 2*t + 1] - mnew);
                S1[j*4 + 2*t]     = p0;
                S1[j*4 + 2*t + 1] = p1;
                lloc += p0 + p1;
            }
            lloc += __shfl_xor_sync(0xffffffffu, lloc, 1);
            lloc += __shfl_xor_sync(0xffffffffu, lloc, 2);
            lstat[t] = lstat[t] * alpha + lloc;
            mstat[t] = mnew;
            #pragma unroll
            for (int j = 0; j < 8; j++) {
                Oacc[j*4 + 2*t]     *= alpha;
                Oacc[j*4 + 2*t + 1] *= alpha;
            }
        }

        const uint32_t vhi_b = buf + FB_VHI;
        const uint32_t vlo_b = buf + FB_VLO;
        #pragma unroll
        for (int t2 = 0; t2 < 4; t2++) {
            uint32_t ah[4], al[4];
            #pragma unroll
            for (int i = 0; i < 4; i++) {
                int jt  = 2*t2 + (i >> 1);
                int off = (i & 1) * 2;
                float p0 = S1[jt*4 + off];
                float p1 = S1[jt*4 + off + 1];
                uint32_t hh = pack_bf16x2(p0, p1);
                ah[i] = hh;
                al[i] = pack_bf16x2(p0 - __uint_as_float(hh << 16),
                                    p1 - __uint_as_float(hh & 0xFFFF0000u));
            }
            const uint32_t row_off =
                (uint32_t)(((t2 * 16 + lmt_k) * 72 + lmt_d) * 2);
            #pragma unroll
            for (int j2 = 0; j2 < 4; j2++) {
                uint32_t off = row_off + (uint32_t)(j2 * 16 * 2);
                uint32_t h0, h1, h2, h3, l0, l1, l2, l3;
                ldmx4t(h0, h1, h2, h3, vhi_b + off);
                ldmx4t(l0, l1, l2, l3, vlo_b + off);
                mma_bf16(&Oacc[(2*j2)*4], ah, h0, h1);
                mma_bf16(&Oacc[(2*j2)*4], al, h0, h1);
                mma_bf16(&Oacc[(2*j2)*4], ah, l0, l1);
                mma_bf16(&Oacc[(2*j2+1)*4], ah, h2, h3);
                mma_bf16(&Oacc[(2*j2+1)*4], al, h2, h3);
                mma_bf16(&Oacc[(2*j2+1)*4], ah, l2, l3);
            }
        }
    }

    float inv0 = 1.f / lstat[0];
    float inv1 = 1.f / lstat[1];
    int rowg = n0 + r0 + row_a;
    #pragma unroll
    for (int j = 0; j < 8; j++) {
        int col = (h << 6) + j * 8 + 2 * colc;
        float a0 = Oacc[j*4 + 0] * inv0, a1 = Oacc[j*4 + 1] * inv0;
        float b0 = Oacc[j*4 + 2] * inv1, b1 = Oacc[j*4 + 3] * inv1;
        long r1o = ((long)b * SEQ + rowg) * 1024 + col;
        long r2o = ((long)b * SEQ + rowg + 8) * 1024 + col;
        uint32_t h1p = pack_bf16x2(a0, a1);
        uint32_t h2p = pack_bf16x2(b0, b1);
        *(uint32_t*)(OBH + r1o) = h1p;
        *(uint32_t*)(OBH + r2o) = h2p;
        *(uint32_t*)(OBL + r1o) =
            pack_bf16x2(a0 - __uint_as_float(h1p << 16),
                        a1 - __uint_as_float(h1p & 0xFFFF0000u));
        *(uint32_t*)(OBL + r2o) =
            pack_bf16x2(b0 - __uint_as_float(h2p << 16),
                        b1 - __uint_as_float(h2p & 0xFFFF0000u));
    }
}

// ---------------------------------------------------------------------------
// Launch — single stream, in-order (R16's multi-stream fork regressed)
// ---------------------------------------------------------------------------
extern "C" void kernel_launch(void* const* d_in, const int* in_sizes, int n_in,
                              void* d_out, int out_size)
{
    const float* x       = (const float*)d_in[0];
    const float* context = (const float*)d_in[1];
    const int*   mask    = (const int*)d_in[2];
    const float* Wq      = (const float*)d_in[3];
    const float* Wkv     = (const float*)d_in[4];
    const float* Wout    = (const float*)d_in[5];
    const float* bout    = (const float*)d_in[6];
    float* out = (float*)d_out;

    float* q;
    cudaGetSymbolAddress((void**)&q, g_q);
    __half *kh, *kl;
    __nv_bfloat16 *vh, *vl;
    cudaGetSymbolAddress((void**)&kh, g_kh);
    cudaGetSymbolAddress((void**)&kl, g_kl);
    cudaGetSymbolAddress((void**)&vh, g_vh);
    cudaGetSymbolAddress((void**)&vl, g_vl);
    __half *xfh, *xfl, *ctfh, *ctfl, *wqfh, *wqfl, *wkfh, *wkfl;
    cudaGetSymbolAddress((void**)&xfh, g_xfh);
    cudaGetSymbolAddress((void**)&xfl, g_xfl);
    cudaGetSymbolAddress((void**)&ctfh, g_ctfh);
    cudaGetSymbolAddress((void**)&ctfl, g_ctfl);
    cudaGetSymbolAddress((void**)&wqfh, g_wqfh);
    cudaGetSymbolAddress((void**)&wqfl, g_wqfl);
    cudaGetSymbolAddress((void**)&wkfh, g_wkfh);
    cudaGetSymbolAddress((void**)&wkfl, g_wkfl);
    __nv_bfloat16 *ctbh, *ctbl, *wvbh, *wvbl, *wobh, *wobl, *obh, *obl;
    cudaGetSymbolAddress((void**)&ctbh, g_ctbh);
    cudaGetSymbolAddress((void**)&ctbl, g_ctbl);
    cudaGetSymbolAddress((void**)&wvbh, g_wvbh);
    cudaGetSymbolAddress((void**)&wvbl, g_wvbl);
    cudaGetSymbolAddress((void**)&wobh, g_wobh);
    cudaGetSymbolAddress((void**)&wobl, g_wobl);
    cudaGetSymbolAddress((void**)&obh, g_obh);
    cudaGetSymbolAddress((void**)&obl, g_obl);

    static bool initd = false;
    if (!initd) {
        cudaFuncSetAttribute(flash_mma,
                             cudaFuncAttributeMaxDynamicSharedMemorySize, FLASH_SMEM);
        cudaFuncSetAttribute(gemm_fp16_qk,
                             cudaFuncAttributeMaxDynamicSharedMemorySize, P16_SMEM);
        cudaFuncSetAttribute(gemm_bf16_ps,
                             cudaFuncAttributeMaxDynamicSharedMemorySize, P16_SMEM);
        initd = true;
    }

    // ---- one fused operand-split launch ----
    fused_split<<<(SPLIT_TASKS + 255) / 256, 256>>>(
        x, context, Wq, Wkv, Wout,
        xfh, xfl, ctfh, ctfl, ctbh, ctbl,
        wqfh, wqfl, wkfh, wkfl, wvbh, wvbl, wobh, wobl);

    // ---- q and k projections merged into one 512-block launch ----
    dim3 gqk(1024 / 128, 4096 / 128, 2);
    gemm_fp16_qk<<<gqk, 256, P16_SMEM>>>(xfh, xfl, wqfh, wqfl, q,
                                         ctfh, ctfl, wkfh, wkfl, kh, kl);

    // ---- v projection (emits per-head bf16 hi/lo) ----
    dim3 gg(1024 / 128, 4096 / 128);
    gemm_bf16_ps<<<gg, 256, P16_SMEM>>>(ctbh, ctbl, wvbh, wvbl, nullptr, nullptr, 2, vh, vl);

    // ---- attention ----
    dim3 grid_attn(SEQ / 64, HEADS, BATCH);
    flash_mma<<<grid_attn, 128, FLASH_SMEM>>>(q, kh, kl, vh, vl, mask, obh, obl);

    // ---- output projection ----
    gemm_bf16_ps<<<gg, 256, P16_SMEM>>>(obh, obl, wobh, wobl, out, bout, 0, nullptr, nullptr);
}